// round 13
// baseline (speedup 1.0000x reference)
#include <cuda_runtime.h>
#include <cuda_fp16.h>
#include <cstdint>

// EnhancedMoEModel: out[b] = sum_e probs[b,e] * sigmoid( relu( relu(x W1e + b1e) W2e + b2e ) W3e + b3e )
// B=524288, D=32, H=64, H2=32, E=8, O=1.
//
// R12 (base = R10, 102.4us): latency attack inside the 128-reg cap.
//  - L2 dependency chain split 4 -> 2+2 (second acc pair zero-init, merged by
//    HADD2 fused into the relu: hmax2(hadd2(d,e),0)). ILP per (j2,r) doubles.
//  - L3 fused into the L2 loop per k-step (kills the la[] array, freeing the
//    registers the split consumes). Net regs ~same, chains half as long.

#define NUM_E 8
// sW1 2048 u4 + sW2 2048 u4 + sW3f 256 u4 + sB1h 256 u32 + sB2h 128 u32 + sB3h 8 u32
#define SMEM_BYTES (2048*16 + 2048*16 + 256*16 + 256*4 + 128*4 + 8*4)

__device__ __forceinline__ uint32_t packh(float lo, float hi) {
    __half2 h = __floats2half2_rn(lo, hi);
    return *reinterpret_cast<uint32_t*>(&h);
}

__device__ __forceinline__ uint32_t hrelu_add(uint32_t a, uint32_t b) {
    __half2 s = __hadd2(*reinterpret_cast<__half2*>(&a), *reinterpret_cast<__half2*>(&b));
    s = __hmax2(s, __floats2half2_rn(0.f, 0.f));
    return *reinterpret_cast<uint32_t*>(&s);
}

__device__ __forceinline__ uint32_t hrelu(uint32_t v) {
    __half2 h = *reinterpret_cast<__half2*>(&v);
    h = __hmax2(h, __floats2half2_rn(0.f, 0.f));
    return *reinterpret_cast<uint32_t*>(&h);
}

// f16-accumulate mma: D (2 regs, f16x2) layout == next-layer A-fragment layout.
__device__ __forceinline__ void mma_f16(uint32_t& d0, uint32_t& d1,
                                        const uint32_t a[4], uint32_t b0, uint32_t b1) {
    asm volatile(
        "mma.sync.aligned.m16n8k16.row.col.f16.f16.f16.f16 "
        "{%0,%1}, {%2,%3,%4,%5}, {%6,%7}, {%0,%1};\n"
        : "+r"(d0), "+r"(d1)
        : "r"(a[0]), "r"(a[1]), "r"(a[2]), "r"(a[3]), "r"(b0), "r"(b1));
}

__global__ void __launch_bounds__(256, 2)
moe_kernel(const float* __restrict__ x,
           const float* __restrict__ probs,
           const float* __restrict__ W1, const float* __restrict__ b1,
           const float* __restrict__ W2, const float* __restrict__ b2,
           const float* __restrict__ W3, const float* __restrict__ b3,
           float* __restrict__ out, int NT32)
{
    extern __shared__ unsigned char smem_raw[];
    uint4*    sW1  = reinterpret_cast<uint4*>(smem_raw);        // 2048: [e][j][lane] = {B(s0), B(s1)}
    uint4*    sW2  = sW1 + 2048;                                // 2048: [e][j2][half][lane]
    uint4*    sW3f = sW2 + 2048;                                // 256: [e][lane] L3 B-frags
    uint32_t* sB1h = reinterpret_cast<uint32_t*>(sW3f + 256);   // 256: [e][j][c] = f16x2 bias pair
    uint32_t* sB2h = sB1h + 256;                                // 128: [e][j2][c]
    uint32_t* sB3h = sB2h + 128;                                // 8:   [e] = f16x2 {b3,b3}

    // ---- one-time weight pre-swizzle into mma B-fragment order (f16x2 pairs) ----
    // B fragment (m16n8k16, col): lane t: b0={B[2c][n],B[2c+1][n]}, b1={B[2c+8][n],B[2c+9][n]},
    // c=t%4, n=t/4. k-step s adds 16 to k.
    for (int idx = threadIdx.x; idx < 2048; idx += blockDim.x) {
        int lanei = idx & 31, j = (idx >> 5) & 7, e = idx >> 8;
        int cc = lanei & 3, nn = lanei >> 2;
        int col = 8 * j + nn;
        const float* base = W1 + (size_t)e * 32 * 64;
        #pragma unroll
        for (int s = 0; s < 2; s++) {
            int k0 = 16 * s + 2 * cc;
            float v00 = base[(k0    ) * 64 + col];
            float v01 = base[(k0 + 1) * 64 + col];
            float v10 = base[(k0 + 8) * 64 + col];
            float v11 = base[(k0 + 9) * 64 + col];
            if (s == 0) { sW1[idx].x = packh(v00, v01); sW1[idx].y = packh(v10, v11); }
            else        { sW1[idx].z = packh(v00, v01); sW1[idx].w = packh(v10, v11); }
        }
    }
    for (int idx = threadIdx.x; idx < 2048; idx += blockDim.x) {
        int lanei = idx & 31, half = (idx >> 5) & 1, j2 = (idx >> 6) & 3, e = idx >> 8;
        int cc = lanei & 3, nn = lanei >> 2;
        int col = 8 * j2 + nn;
        const float* base = W2 + (size_t)e * 64 * 32;
        uint4 outv;
        #pragma unroll
        for (int t = 0; t < 2; t++) {
            int s2 = 2 * half + t;
            int k0 = 16 * s2 + 2 * cc;
            float v00 = base[(k0    ) * 32 + col];
            float v01 = base[(k0 + 1) * 32 + col];
            float v10 = base[(k0 + 8) * 32 + col];
            float v11 = base[(k0 + 9) * 32 + col];
            if (t == 0) { outv.x = packh(v00, v01); outv.y = packh(v10, v11); }
            else        { outv.z = packh(v00, v01); outv.w = packh(v10, v11); }
        }
        sW2[idx] = outv;
    }
    // L3 B-fragments: B[32,8] with col 0 = w3, cols 1..7 = 0 (nonzero only for nn==0).
    for (int idx = threadIdx.x; idx < 256; idx += blockDim.x) {
        int lanei = idx & 31, e = idx >> 5;
        int cc = lanei & 3, nn = lanei >> 2;
        uint4 v = make_uint4(0u, 0u, 0u, 0u);
        if (nn == 0) {
            const float* w3 = W3 + e * 32;
            v.x = packh(w3[2 * cc],      w3[2 * cc + 1]);
            v.y = packh(w3[2 * cc + 8],  w3[2 * cc + 9]);
            v.z = packh(w3[2 * cc + 16], w3[2 * cc + 17]);
            v.w = packh(w3[2 * cc + 24], w3[2 * cc + 25]);
        }
        sW3f[idx] = v;
    }
    for (int idx = threadIdx.x; idx < 256; idx += blockDim.x) {
        int cc = idx & 3, j = (idx >> 2) & 7, e = idx >> 5;
        int col = 8 * j + 2 * cc;
        sB1h[idx] = packh(b1[e * 64 + col], b1[e * 64 + col + 1]);
    }
    for (int idx = threadIdx.x; idx < 128; idx += blockDim.x) {
        int cc = idx & 3, j2 = (idx >> 2) & 3, e = idx >> 4;
        int col = 8 * j2 + 2 * cc;
        sB2h[idx] = packh(b2[e * 32 + col], b2[e * 32 + col + 1]);
    }
    if (threadIdx.x < 8) sB3h[threadIdx.x] = packh(b3[threadIdx.x], b3[threadIdx.x]);
    __syncthreads();

    const int lane = threadIdx.x & 31;
    const int c = lane & 3;       // quad column index
    const int rq = lane >> 2;     // row within 8-row group
    const int warp_global = blockIdx.x * 8 + (threadIdx.x >> 5);
    const int nwarps = gridDim.x * 8;

    for (int tile = warp_global; tile < NT32; tile += nwarps) {
        const int rowbase = tile << 5;

        // ---- load x A-fragments for 2 subtiles (f32 -> f16x2 on the fly) ----
        uint32_t xa[2][2][4];
        #pragma unroll
        for (int r = 0; r < 2; r++) {
            const float* xr0 = x + (size_t)(rowbase + r * 16 + rq) * 32;
            const float* xr1 = xr0 + 8 * 32;
            #pragma unroll
            for (int s = 0; s < 2; s++) {
                const int col = 16 * s + 2 * c;
                float2 v00 = *reinterpret_cast<const float2*>(xr0 + col);
                float2 v10 = *reinterpret_cast<const float2*>(xr1 + col);
                float2 v01 = *reinterpret_cast<const float2*>(xr0 + col + 8);
                float2 v11 = *reinterpret_cast<const float2*>(xr1 + col + 8);
                xa[r][s][0] = packh(v00.x, v00.y);
                xa[r][s][1] = packh(v10.x, v10.y);
                xa[r][s][2] = packh(v01.x, v01.y);
                xa[r][s][3] = packh(v11.x, v11.y);
            }
        }

        float oa[2][2];
        oa[0][0] = oa[0][1] = oa[1][0] = oa[1][1] = 0.f;

        #pragma unroll 1
        for (int e = 0; e < NUM_E; e++) {
            // ---- layer 1: [32,32] @ [32,64]; f16-acc D regs ARE next A-fragments ----
            uint32_t ha[2][4][4];
            const uint4* w1e = sW1 + e * 256 + lane;
            #pragma unroll
            for (int j = 0; j < 8; j++) {
                uint4 B = w1e[j * 32];
                uint32_t bb = sB1h[e * 32 + j * 4 + c];
                const int s2 = j >> 1, h = j & 1;
                #pragma unroll
                for (int r = 0; r < 2; r++) {
                    uint32_t d0 = bb, d1 = bb;   // bias folded into acc init
                    mma_f16(d0, d1, xa[r][0], B.x, B.y);
                    mma_f16(d0, d1, xa[r][1], B.z, B.w);
                    ha[r][s2][h * 2 + 0] = hrelu(d0);
                    ha[r][s2][h * 2 + 1] = hrelu(d1);
                }
            }

            // ---- layers 2+3 fused. L2 chain split 2+2; L3 HMMA per k-step s3. ----
            const uint4* w2e = sW2 + e * 256 + lane;
            uint4 W3v = sW3f[e * 32 + lane];
            uint32_t b3h = sB3h[e];
            uint32_t d3[2][2];                       // [r][reg] L3 accumulators
            d3[0][0] = b3h; d3[0][1] = b3h;
            d3[1][0] = b3h; d3[1][1] = b3h;
            #pragma unroll
            for (int s3 = 0; s3 < 2; s3++) {
                uint32_t lf[2][4];                   // [r][frag] L3 A-fragments, this k-step
                #pragma unroll
                for (int h = 0; h < 2; h++) {
                    const int j2 = 2 * s3 + h;
                    uint4 Ca = w2e[(j2 * 2 + 0) * 32];   // s2 = 0,1
                    uint4 Cb = w2e[(j2 * 2 + 1) * 32];   // s2 = 2,3
                    uint32_t bb2 = sB2h[e * 16 + j2 * 4 + c];
                    #pragma unroll
                    for (int r = 0; r < 2; r++) {
                        uint32_t d0 = bb2, d1 = bb2;     // Ca-half chain (carries bias)
                        uint32_t f0 = 0u,  f1 = 0u;      // Cb-half chain (zero init)
                        mma_f16(d0, d1, ha[r][0], Ca.x, Ca.y);
                        mma_f16(f0, f1, ha[r][2], Cb.x, Cb.y);
                        mma_f16(d0, d1, ha[r][1], Ca.z, Ca.w);
                        mma_f16(f0, f1, ha[r][3], Cb.z, Cb.w);
                        lf[r][h * 2 + 0] = hrelu_add(d0, f0);
                        lf[r][h * 2 + 1] = hrelu_add(d1, f1);
                    }
                }
                const uint32_t B0 = (s3 == 0) ? W3v.x : W3v.z;
                const uint32_t B1 = (s3 == 0) ? W3v.y : W3v.w;
                #pragma unroll
                for (int r = 0; r < 2; r++)
                    mma_f16(d3[r][0], d3[r][1], lf[r], B0, B1);
            }

            // ---- epilogue: z in lo half of d3 regs (valid at c==0), sigmoid + weight ----
            #pragma unroll
            for (int r = 0; r < 2; r++) {
                float z0 = __low2float(*reinterpret_cast<__half2*>(&d3[r][0]));
                float z1 = __low2float(*reinterpret_cast<__half2*>(&d3[r][1]));
                float s0 = 1.f / (1.f + __expf(-z0));
                float s1 = 1.f / (1.f + __expf(-z1));
                oa[r][0] += s0 * probs[(size_t)(rowbase + r * 16 + rq) * NUM_E + e];
                oa[r][1] += s1 * probs[(size_t)(rowbase + r * 16 + 8 + rq) * NUM_E + e];
            }
        }

        if (c == 0) {
            #pragma unroll
            for (int r = 0; r < 2; r++) {
                out[rowbase + r * 16 + rq]     = oa[r][0];
                out[rowbase + r * 16 + 8 + rq] = oa[r][1];
            }
        }
    }
}

extern "C" void kernel_launch(void* const* d_in, const int* in_sizes, int n_in,
                              void* d_out, int out_size) {
    const float* x     = (const float*)d_in[0];
    const float* probs = (const float*)d_in[1];
    const float* W1    = (const float*)d_in[2];
    const float* b1    = (const float*)d_in[3];
    const float* W2    = (const float*)d_in[4];
    const float* b2    = (const float*)d_in[5];
    const float* W3    = (const float*)d_in[6];
    const float* b3    = (const float*)d_in[7];
    float* out = (float*)d_out;

    const int B    = in_sizes[0] / 32;
    const int NT32 = B / 32;   // 16384 warp-tiles of 32 rows

    cudaFuncSetAttribute(moe_kernel, cudaFuncAttributeMaxDynamicSharedMemorySize, SMEM_BYTES);
    cudaFuncSetAttribute(moe_kernel, cudaFuncAttributePreferredSharedMemoryCarveout, 100);

    // 296 persistent CTAs (2 per SM), 2368 warps striding over 16384 tiles
    moe_kernel<<<296, 256, SMEM_BYTES>>>(x, probs, W1, b1, W2, b2, W3, b3, out, NT32);
}